// round 15
// baseline (speedup 1.0000x reference)
#include <cuda_runtime.h>
#include <cuda_fp16.h>
#include <math.h>
#include <stdint.h>

#define BB 2
#define TT 32
#define LLE 64
#define DD 1024
#define HH 16
#define HD 64
#define NWIN 8
#define SSQ 512
#define AROWS 4096
#define TLTOK 2048
#define BTLR 4096
#define DG 2048
#define K3D 3072
#define FEATSZ ((size_t)BTLR * DD)
#define QSPAN ((size_t)NWIN * HH * SSQ * HD)

// GEMM smem (u32): A 2 ktiles x 256 rows x 12, B 2 ktiles x 128 x 12, x2 buf
#define AKT 3072
#define ABUF (2 * AKT)
#define BKT 1536
#define BBUF (2 * BKT)
#define BOFFU (2 * ABUF)
#define GSMEMB ((BOFFU + 2 * BBUF) * 4)   // 73728 B
// attn smem: QP 256x36 + 2 x (K 64x36 + V 64x36)
#define KVBUF (2 * 64 * 36)               // 4608 u32 per buffer (K+V)
#define ASMEM ((256 * 36 + 2 * KVBUF) * 4)   // 73728 B

__device__ __half g_Q[3 * QSPAN];
__device__ __half g_K[3 * QSPAN];
__device__ __half g_Vt[3 * QSPAN];                      // [j][bh][d][s]
__device__ __half g_Oh[(size_t)3 * AROWS * DD];
__device__ __half g_Xh[(size_t)3 * BTLR * DD];          // fp16 modalities
__device__ __half g_featsh[(size_t)3 * BTLR * DD];
__device__ __half g_Gh[(size_t)BTLR * DG];
__device__ __half g_Wh[(size_t)12 * DD * DD + (size_t)DG * K3D];

__device__ __forceinline__ float gelu_f(float x) {
    return 0.5f * x * (1.0f + erff(x * 0.70710678118654752440f));
}
__device__ __forceinline__ uint32_t pack2(float lo, float hi) {
    uint32_t u;
    asm("cvt.rn.f16x2.f32 %0, %1, %2;" : "=r"(u) : "f"(hi), "f"(lo));
    return u;
}
__device__ __forceinline__ uint32_t smem_u32(const void* p) {
    uint32_t a;
    asm("{ .reg .u64 t; cvta.to.shared.u64 t, %1; cvt.u32.u64 %0, t; }" : "=r"(a) : "l"(p));
    return a;
}
__device__ __forceinline__ void ldsm4(uint32_t* r, uint32_t sa) {
    asm volatile("ldmatrix.sync.aligned.m8n8.x4.shared.b16 {%0,%1,%2,%3}, [%4];"
        : "=r"(r[0]), "=r"(r[1]), "=r"(r[2]), "=r"(r[3]) : "r"(sa));
}
__device__ __forceinline__ void mma16(float* d, const uint32_t* a, const uint32_t* b) {
    asm volatile("mma.sync.aligned.m16n8k16.row.col.f32.f16.f16.f32 "
        "{%0,%1,%2,%3}, {%4,%5,%6,%7}, {%8,%9}, {%0,%1,%2,%3};"
        : "+f"(d[0]), "+f"(d[1]), "+f"(d[2]), "+f"(d[3])
        : "r"(a[0]), "r"(a[1]), "r"(a[2]), "r"(a[3]), "r"(b[0]), "r"(b[1]));
}

// ---------------- prepass: modalities fp32 -> fp16 ----------------
__global__ __launch_bounds__(256) void conv_k(
    const float* __restrict__ a, const float* __restrict__ v,
    const float* __restrict__ im)
{
    const float* src = (blockIdx.y == 0) ? a : (blockIdx.y == 1) ? v : im;
    __half* dst = g_Xh + (size_t)blockIdx.y * FEATSZ;
    const size_t i = ((size_t)blockIdx.x * 256 + threadIdx.x) * 8;
    float4 f0 = *(const float4*)(src + i);
    float4 f1 = *(const float4*)(src + i + 4);
    uint4 o = make_uint4(pack2(f0.x, f0.y), pack2(f0.z, f0.w),
                         pack2(f1.x, f1.y), pack2(f1.z, f1.w));
    *(uint4*)(dst + i) = o;
}

// ---------------- weight transposes -> fp16 [n][k] ----------------
__global__ __launch_bounds__(256) void transW_k(
    const float* __restrict__ Wq, const float* __restrict__ Wk,
    const float* __restrict__ Wv, const float* __restrict__ Wp)
{
    __shared__ float tile[32][33];
    const int z = blockIdx.z;
    const float* W = (z < 3) ? Wq + (size_t)z * DD * DD
                   : (z < 6) ? Wk + (size_t)(z - 3) * DD * DD
                   : (z < 9) ? Wv + (size_t)(z - 6) * DD * DD
                             : Wp + (size_t)(z - 9) * DD * DD;
    __half* Wt = g_Wh + (size_t)z * DD * DD;
    const int n0 = blockIdx.x << 5, k0 = blockIdx.y << 5;
    const int tx = threadIdx.x & 31, ty = threadIdx.x >> 5;
    #pragma unroll
    for (int j = 0; j < 32; j += 8)
        tile[ty + j][tx] = W[(size_t)(k0 + ty + j) * DD + n0 + tx];
    __syncthreads();
    const int tp = threadIdx.x & 15, nr = threadIdx.x >> 4;
    #pragma unroll
    for (int j = 0; j < 2; j++) {
        const int nn = nr + j * 16;
        __half2 hv = __floats2half2_rn(tile[2 * tp][nn], tile[2 * tp + 1][nn]);
        *(__half2*)(Wt + (size_t)(n0 + nn) * DD + k0 + 2 * tp) = hv;
    }
}
__global__ __launch_bounds__(256) void transG_k(const float* __restrict__ Wg1)
{
    __shared__ float tile[32][33];
    __half* Wt = g_Wh + (size_t)12 * DD * DD;
    const int n0 = blockIdx.x << 5, k0 = blockIdx.y << 5;
    const int tx = threadIdx.x & 31, ty = threadIdx.x >> 5;
    #pragma unroll
    for (int j = 0; j < 32; j += 8)
        tile[ty + j][tx] = Wg1[(size_t)(k0 + ty + j) * DG + n0 + tx];
    __syncthreads();
    const int tp = threadIdx.x & 15, nr = threadIdx.x >> 4;
    #pragma unroll
    for (int j = 0; j < 2; j++) {
        const int nn = nr + j * 16;
        __half2 hv = __floats2half2_rn(tile[2 * tp][nn], tile[2 * tp + 1][nn]);
        *(__half2*)(Wt + (size_t)(n0 + nn) * K3D + k0 + 2 * tp) = hv;
    }
}

// ---------------------------------------------------------------------------
// fp16 mma GEMM: CTA 256x128, 512 threads, 16 warps (8m x 2n), warp 32x64,
// K-chunk 32 (2 ktiles), double-buffered (R11 core).
// MODE 0 = QKV fused (grid (24,48): bx>>3 = 0 Q,1 K,2 V)
// MODE 2 = out-proj (grid (8,48));  MODE 3 = gate L1 (grid (16,16)).
// ---------------------------------------------------------------------------
template<int MODE>
__global__ __launch_bounds__(512) void tgemm_k(
    const float* __restrict__ p0, const float* __restrict__ p1,
    const float* __restrict__ p2, const float* __restrict__ p3,
    const float* __restrict__ p4, int K)
{
    extern __shared__ uint32_t smu[];
    const uint32_t sb = smem_u32(smu);

    const int tid = threadIdx.x;
    const int wid = tid >> 5, ln = tid & 31;
    const int warpm = wid & 7, warpn = wid >> 3;
    const int g = ln >> 2, t = ln & 3;

    int j, m0, n0, qkv = 0;
    if (MODE == 3) { j = 0; m0 = blockIdx.y << 8; n0 = blockIdx.x << 7; }
    else {
        j = blockIdx.y >> 4; m0 = (blockIdx.y & 15) << 8;
        if (MODE == 0) { qkv = blockIdx.x >> 3; n0 = (blockIdx.x & 7) << 7; }
        else           { n0 = blockIdx.x << 7; }
    }

    // staging geometry
    const int arowS = tid >> 1, ktA = tid & 1;
    const int browS = tid >> 2, ktB = (tid >> 1) & 1, hbB = tid & 1;

    // ldmatrix per-lane offsets (bytes, within one ktile buffer)
    const int arow_l = ((ln >> 3) & 1) * 8 + (ln & 7);
    const int akh = ln >> 4;
    int aoff[2];
    #pragma unroll
    for (int mi = 0; mi < 2; mi++)
        aoff[mi] = (((warpm * 32 + mi * 16 + arow_l) * 12) + akh * 4) << 2;
    const int brow_l = ((ln >> 4) * 8) + (ln & 7);
    const int bkh = (ln >> 3) & 1;
    int boff[4];
    #pragma unroll
    for (int pi = 0; pi < 4; pi++)
        boff[pi] = (((warpn * 64 + pi * 16 + brow_l) * 12) + bkh * 4) << 2;

    // A pointer
    const __half* Am;
    size_t arow;
    {
        const int ksl = (j == 1) ? 0 : 1;   // kv input: video,audio,video
        if (MODE == 0) {
            const int r = m0 + arowS;
            const int bw = r >> 9, s = r & 511;
            const int b = bw >> 2, w = bw & 3;
            const int st = s >> 6, l = s & 63;
            const int tt = (w * 8 + st + 4) & 31;    // roll(-SH) gather
            arow = (size_t)((b * TT + tt) * LLE + l) << 10;
            Am = g_Xh + (size_t)((qkv == 0) ? j : ksl) * FEATSZ;
        } else if (MODE == 2) {
            arow = (size_t)(m0 + arowS) << 10;
            Am = g_Oh + (size_t)j * AROWS * DD;
        } else {
            arow = (size_t)(m0 + arowS) << 10;
            Am = g_featsh;
        }
    }
    // B pointer
    size_t wh_off;
    if (MODE == 0)      wh_off = (size_t)(qkv * 3 + j) * DD * DD;
    else if (MODE == 2) wh_off = (size_t)(9 + j) * DD * DD;
    else                wh_off = (size_t)12 * DD * DD;
    const __half* Bw = g_Wh + wh_off + (size_t)(n0 + browS) * K + ktB * 16 + hbB * 8;

    uint4 pa[2], pb;
#define LOADG(kc) do {                                                            \
    const __half* as_;                                                            \
    if (MODE == 3) {                                                              \
        const int kg_ = (kc) + ktA * 16;                                          \
        as_ = g_featsh + (size_t)(kg_ >> 10) * FEATSZ + arow + (kg_ & 1023);      \
    } else {                                                                      \
        as_ = Am + arow + (kc) + ktA * 16;                                        \
    }                                                                             \
    pa[0] = *(const uint4*)(as_);                                                 \
    pa[1] = *(const uint4*)(as_ + 8);                                             \
    pb = *(const uint4*)(Bw + (kc));                                              \
} while (0)
#define STOREG(bf_) do {                                                          \
    uint32_t* a0_ = smu + (bf_) * ABUF + ktA * AKT + arowS * 12;                  \
    *(uint4*)a0_ = pa[0]; *(uint4*)(a0_ + 4) = pa[1];                             \
    uint32_t* b0_ = smu + BOFFU + (bf_) * BBUF + ktB * BKT + browS * 12 + hbB * 4;\
    *(uint4*)b0_ = pb;                                                            \
} while (0)

    float acc[2][8][4];
    #pragma unroll
    for (int i = 0; i < 2; i++)
        #pragma unroll
        for (int jj = 0; jj < 8; jj++)
            #pragma unroll
            for (int q = 0; q < 4; q++) acc[i][jj][q] = 0.f;

    const int NC = K >> 5;
    LOADG(0);
    STOREG(0);
    __syncthreads();

    for (int c = 0; c < NC; c++) {
        if (c + 1 < NC) LOADG((c + 1) << 5);
        const int bsel = c & 1;
        #pragma unroll
        for (int kt = 0; kt < 2; kt++) {
            const uint32_t ab = sb + ((bsel * ABUF + kt * AKT) << 2);
            const uint32_t bb = sb + ((BOFFU + bsel * BBUF + kt * BKT) << 2);
            uint32_t af[2][4], bfr[4][4];
            #pragma unroll
            for (int mi = 0; mi < 2; mi++)
                ldsm4(af[mi], ab + aoff[mi]);
            #pragma unroll
            for (int pi = 0; pi < 4; pi++)
                ldsm4(bfr[pi], bb + boff[pi]);
            #pragma unroll
            for (int mi = 0; mi < 2; mi++)
                #pragma unroll
                for (int ni = 0; ni < 8; ni++)
                    mma16(acc[mi][ni], af[mi], &bfr[ni >> 1][(ni & 1) * 2]);
        }
        if (c + 1 < NC) STOREG((c + 1) & 1);
        __syncthreads();
    }

    // ---- epilogue ----
    const float* bias =
        (MODE == 0) ? ((qkv == 0) ? p0 : (qkv == 1) ? p1 : p2) + j * DD :
        (MODE == 2) ? p0 + j * DD : p0;
    const float* nw =
        (MODE == 0 && qkv == 0) ? p3 + j * HD :
        (MODE == 0 && qkv == 1) ? p4 + j * HD : nullptr;
    const float nscale = (MODE == 0 && qkv == 0) ? 0.125f : 1.0f;

    float2 bz[8], nz[8];
    #pragma unroll
    for (int ni = 0; ni < 8; ni++)
        bz[ni] = *(const float2*)(bias + n0 + warpn * 64 + ni * 8 + 2 * t);
    if (nw) {
        #pragma unroll
        for (int ni = 0; ni < 8; ni++)
            nz[ni] = *(const float2*)(nw + ni * 8 + 2 * t);
    }

    #pragma unroll
    for (int mi = 0; mi < 2; mi++)
    #pragma unroll
    for (int rh = 0; rh < 2; rh++) {
        const int m = m0 + warpm * 32 + mi * 16 + rh * 8 + g;
        float v[16];
        #pragma unroll
        for (int ni = 0; ni < 8; ni++) {
            v[2*ni]   = acc[mi][ni][2*rh]   + bz[ni].x;
            v[2*ni+1] = acc[mi][ni][2*rh+1] + bz[ni].y;
        }
        if (MODE == 0) {
            const int bw = m >> 9, s = m & 511;
            const int h = (n0 + warpn * 64) >> 6;
            if (nw) {
                float ss = 0.f;
                #pragma unroll
                for (int jj = 0; jj < 16; jj++) ss = fmaf(v[jj], v[jj], ss);
                ss += __shfl_xor_sync(0xffffffffu, ss, 1);
                ss += __shfl_xor_sync(0xffffffffu, ss, 2);
                const float rs = rsqrtf(ss * (1.f / 64.f) + 1e-6f) * nscale;
                #pragma unroll
                for (int ni = 0; ni < 8; ni++) {
                    v[2*ni]   *= rs * nz[ni].x;
                    v[2*ni+1] *= rs * nz[ni].y;
                }
            }
            if (qkv == 2) {                 // V: transposed fp16 store
                __half* Vb = g_Vt + (size_t)j * QSPAN;
                #pragma unroll
                for (int ni = 0; ni < 8; ni++) {
                    const int d = ni * 8 + 2 * t;
                    size_t base = (((size_t)(bw * HH + h) * 64 + d) << 9) + s;
                    Vb[base]       = __float2half_rn(v[2*ni]);
                    Vb[base + 512] = __float2half_rn(v[2*ni+1]);
                }
            } else {
                uint32_t* Cp = (uint32_t*)((qkv == 0) ? (g_Q + (size_t)j * QSPAN)
                                                      : (g_K + (size_t)j * QSPAN));
                const size_t rowb = (((size_t)(bw * HH + h) * 512 + s)) * 32;
                #pragma unroll
                for (int ni = 0; ni < 8; ni++)
                    Cp[rowb + ni * 4 + t] = pack2(v[2*ni], v[2*ni+1]);
            }
        } else if (MODE == 2) {
            const int bw = m >> 9, s = m & 511;
            const int b = bw >> 2, w = bw & 3;
            const int st = s >> 6, l = s & 63;
            const int tg = (w * 8 + st + 4) & 31;    // roll(+SH) scatter
            const size_t rowo = ((size_t)(b * TLTOK + tg * LLE + l) << 10)
                              + n0 + warpn * 64 + 2 * t;
            const float* rbase = (j == 0) ? p1 : (j == 1) ? p2 : p3;
            const float* rr = rbase + ((size_t)((b * TT + tg) * LLE + l) << 10)
                            + n0 + warpn * 64 + 2 * t;
            uint32_t* fh = (uint32_t*)(g_featsh + (size_t)j * FEATSZ + rowo);
            #pragma unroll
            for (int ni = 0; ni < 8; ni++) {
                float2 r2 = *(const float2*)(rr + ni * 8);
                fh[ni * 4] = pack2(v[2*ni] + r2.x, v[2*ni+1] + r2.y);
            }
        } else {
            uint32_t* gp = (uint32_t*)(g_Gh + (size_t)m * DG + n0 + warpn * 64 + 2 * t);
            #pragma unroll
            for (int ni = 0; ni < 8; ni++)
                gp[ni * 4] = pack2(gelu_f(v[2*ni]), gelu_f(v[2*ni+1]));
        }
    }
}

// ---------------------------------------------------------------------------
// Flash attention: 512 threads, 256 q-rows per CTA (2 q-tiles), 16 warps of
// 16 q-rows; K/V staged once per CTA per tile, double-buffered w/ prefetch.
// grid (384, 2): j = bx>>7, bh = bx&127, q-half = by.
// ---------------------------------------------------------------------------
__global__ __launch_bounds__(512, 1) void attn_mma_k(const float* __restrict__ rpb0)
{
    extern __shared__ uint32_t sma[];
    uint32_t* QP = sma;                       // 256*36
    const uint32_t sa0 = smem_u32(sma);
    const uint32_t qb_sa = sa0;

    const int tid = threadIdx.x;
    const int wid = tid >> 5, ln = tid & 31;
    const int g = ln >> 2, t = ln & 3;
    const int j = blockIdx.x >> 7, bhl = blockIdx.x & 127;
    const int qt = blockIdx.y;
    const int h = bhl & 15, bw = bhl >> 4;
    const int q0 = qt << 8;                   // 256 q rows per CTA
    const int tq = (qt << 2) + (wid >> 2);    // temporal coord of warp's rows
    const int mrow = wid << 4;
    const float* rpb = rpb0 + j * 15 * HH;

    const uint32_t* Qb  = (const uint32_t*)(g_Q  + (size_t)j * QSPAN);
    const uint32_t* Kb  = (const uint32_t*)(g_K  + (size_t)j * QSPAN);
    const uint32_t* Vtb = (const uint32_t*)(g_Vt + (size_t)j * QSPAN);

    const int arow_l = ((ln >> 3) & 1) * 8 + (ln & 7);
    const int akh = ln >> 4;
    const int aoff = ((mrow + arow_l) * 36 + akh * 4) << 2;
    const int brow_l = ((ln >> 4) * 8) + (ln & 7);
    const int bkh = (ln >> 3) & 1;
    int boff[4];
    #pragma unroll
    for (int pi = 0; pi < 4; pi++)
        boff[pi] = ((pi * 16 + brow_l) * 36 + bkh * 4) << 2;

    {   // stage Q: 256 rows x 32 u32, 512 threads x 16 u32
        const int r = tid >> 1, cu = (tid & 1) << 4;
        const uint32_t* qs = Qb + ((size_t)(bhl * 512 + q0 + r)) * 32 + cu;
        #pragma unroll
        for (int u = 0; u < 4; u++)
            *(uint4*)&QP[r * 36 + cu + u * 4] = *(const uint4*)(qs + u * 4);
    }
    __syncthreads();

    uint32_t af[4][4];
    #pragma unroll
    for (int kt4 = 0; kt4 < 4; kt4++)
        ldsm4(af[kt4], qb_sa + aoff + (kt4 << 5));
    __syncthreads();

    float oc[8][4];
    #pragma unroll
    for (int i = 0; i < 8; i++)
        #pragma unroll
        for (int q = 0; q < 4; q++) oc[i][q] = 0.f;
    float m_i[2] = {-1e30f, -1e30f}, l_i[2] = {0.f, 0.f};

    const int sr = tid >> 3, scu = (tid & 7) << 2;   // 512 thr: 1 uint4 each

    uint4 pk, pv;
#define LOADKV(kt_) do {                                                          \
    pk = *(const uint4*)(Kb + ((size_t)(bhl * 512 + (kt_) * 64 + sr)) * 32 + scu);\
    pv = *(const uint4*)(Vtb + ((size_t)(bhl * 64 + sr)) * 256 + (kt_) * 32 + scu);\
} while (0)

    LOADKV(0);

    for (int kt = 0; kt < 8; kt++) {
        const float bias_s = rpb[(tq - kt + 7) * HH + h];
        const int buf = kt & 1;
        uint32_t* Ktb  = sma + 256 * 36 + buf * KVBUF;
        uint32_t* Vtbs = Ktb + 64 * 36;
        *(uint4*)&Ktb[sr * 36 + scu]  = pk;
        *(uint4*)&Vtbs[sr * 36 + scu] = pv;
        __syncthreads();
        if (kt < 7) LOADKV(kt + 1);
        const uint32_t kb_sa = sa0 + ((256 * 36 + buf * KVBUF) << 2);
        const uint32_t vb_sa = kb_sa + (64 * 36 << 2);

        float sc[8][4];
        #pragma unroll
        for (int i = 0; i < 8; i++)
            #pragma unroll
            for (int q = 0; q < 4; q++) sc[i][q] = 0.f;
        #pragma unroll
        for (int kt4 = 0; kt4 < 4; kt4++) {
            uint32_t bfr[4][4];
            #pragma unroll
            for (int pi = 0; pi < 4; pi++)
                ldsm4(bfr[pi], kb_sa + boff[pi] + (kt4 << 5));
            #pragma unroll
            for (int ni = 0; ni < 8; ni++)
                mma16(sc[ni], af[kt4], &bfr[ni >> 1][(ni & 1) * 2]);
        }

        #pragma unroll
        for (int hr = 0; hr < 2; hr++) {
            float mx = -1e30f;
            #pragma unroll
            for (int ni = 0; ni < 8; ni++)
                mx = fmaxf(mx, fmaxf(sc[ni][2*hr], sc[ni][2*hr+1]));
            mx += bias_s;
            mx = fmaxf(mx, __shfl_xor_sync(0xffffffffu, mx, 1));
            mx = fmaxf(mx, __shfl_xor_sync(0xffffffffu, mx, 2));
            const float mn = fmaxf(m_i[hr], mx);
            const float fac = __expf(m_i[hr] - mn);
            m_i[hr] = mn;
            float sum = 0.f;
            const int prow = (mrow + hr * 8 + g) * 36;
            #pragma unroll
            for (int ni = 0; ni < 8; ni++) {
                float p0 = __expf(sc[ni][2*hr]   + bias_s - mn);
                float p1 = __expf(sc[ni][2*hr+1] + bias_s - mn);
                sum += p0 + p1;
                QP[prow + ni * 4 + t] = pack2(p0, p1);
            }
            sum += __shfl_xor_sync(0xffffffffu, sum, 1);
            sum += __shfl_xor_sync(0xffffffffu, sum, 2);
            l_i[hr] = l_i[hr] * fac + sum;
            #pragma unroll
            for (int ni = 0; ni < 8; ni++) {
                oc[ni][2*hr]   *= fac;
                oc[ni][2*hr+1] *= fac;
            }
        }
        __syncwarp();   // P is warp-private (own 16 rows)

        #pragma unroll
        for (int kp = 0; kp < 4; kp++) {
            uint32_t pf[4], vfr[4][4];
            ldsm4(pf, qb_sa + aoff + (kp << 5));
            #pragma unroll
            for (int pi = 0; pi < 4; pi++)
                ldsm4(vfr[pi], vb_sa + boff[pi] + (kp << 5));
            #pragma unroll
            for (int ni = 0; ni < 8; ni++)
                mma16(oc[ni], pf, &vfr[ni >> 1][(ni & 1) * 2]);
        }
    }

    const float inv0 = 1.0f / l_i[0], inv1 = 1.0f / l_i[1];
    #pragma unroll
    for (int hr = 0; hr < 2; hr++) {
        const float inv = hr ? inv1 : inv0;
        const int row = q0 + mrow + hr * 8 + g;
        uint32_t* dst = (uint32_t*)g_Oh
            + ((size_t)j * AROWS + bw * SSQ + row) * 512 + h * 32 + t;
        #pragma unroll
        for (int ni = 0; ni < 8; ni++)
            dst[ni * 4] = pack2(oc[ni][2*hr] * inv, oc[ni][2*hr+1] * inv);
    }
}

// ---------------------------------------------------------------------------
// Gate logits (fp16 G) + softmax + fuse (fp16 feats).
// ---------------------------------------------------------------------------
__global__ __launch_bounds__(256) void gate_fuse_k(const float* __restrict__ Wg2,
                                                   const float* __restrict__ bg2,
                                                   float* __restrict__ out)
{
    const int row = blockIdx.x, tid = threadIdx.x;
    const __half2* gh = (const __half2*)(g_Gh + (size_t)row * DG);
    float s0 = 0.f, s1 = 0.f, s2 = 0.f;
    for (int kp = tid; kp < DG / 2; kp += 256) {
        float2 x2 = __half22float2(gh[kp]);
        const int k = kp * 2;
        s0 = fmaf(x2.x, Wg2[k*3+0], fmaf(x2.y, Wg2[k*3+3], s0));
        s1 = fmaf(x2.x, Wg2[k*3+1], fmaf(x2.y, Wg2[k*3+4], s1));
        s2 = fmaf(x2.x, Wg2[k*3+2], fmaf(x2.y, Wg2[k*3+5], s2));
    }
    #pragma unroll
    for (int m = 16; m; m >>= 1) {
        s0 += __shfl_xor_sync(0xffffffffu, s0, m);
        s1 += __shfl_xor_sync(0xffffffffu, s1, m);
        s2 += __shfl_xor_sync(0xffffffffu, s2, m);
    }
    __shared__ float red[3][8];
    __shared__ float gl[3];
    int wid = tid >> 5, lane = tid & 31;
    if (lane == 0) { red[0][wid]=s0; red[1][wid]=s1; red[2][wid]=s2; }
    __syncthreads();
    if (tid < 3) {
        float s = bg2[tid];
        #pragma unroll
        for (int w = 0; w < 8; w++) s += red[tid][w];
        gl[tid] = s;
    }
    __syncthreads();
    float a0 = gl[0], a1 = gl[1], a2 = gl[2];
    float mx = fmaxf(a0, fmaxf(a1, a2));
    float e0 = __expf(a0-mx), e1 = __expf(a1-mx), e2 = __expf(a2-mx);
    float inv = 1.0f / (e0 + e1 + e2);
    e0 *= inv; e1 *= inv; e2 *= inv;
    const uint2* f0 = (const uint2*)(g_featsh + (size_t)0*FEATSZ + (size_t)row*DD);
    const uint2* f1 = (const uint2*)(g_featsh + (size_t)1*FEATSZ + (size_t)row*DD);
    const uint2* f2 = (const uint2*)(g_featsh + (size_t)2*FEATSZ + (size_t)row*DD);
    float4* o4 = (float4*)(out + (size_t)row * DD);
    uint2 u0 = f0[tid], u1 = f1[tid], u2 = f2[tid];
    float2 a_0 = __half22float2(*(__half2*)&u0.x), a_1 = __half22float2(*(__half2*)&u0.y);
    float2 b_0 = __half22float2(*(__half2*)&u1.x), b_1 = __half22float2(*(__half2*)&u1.y);
    float2 c_0 = __half22float2(*(__half2*)&u2.x), c_1 = __half22float2(*(__half2*)&u2.y);
    o4[tid] = make_float4(e0*a_0.x + e1*b_0.x + e2*c_0.x,
                          e0*a_0.y + e1*b_0.y + e2*c_0.y,
                          e0*a_1.x + e1*b_1.x + e2*c_1.x,
                          e0*a_1.y + e1*b_1.y + e2*c_1.y);
}

// ---------------------------------------------------------------------------
// Launch
// ---------------------------------------------------------------------------
extern "C" void kernel_launch(void* const* d_in, const int* in_sizes, int n_in,
                              void* d_out, int out_size)
{
    const float* audio = (const float*)d_in[0];
    const float* video = (const float*)d_in[1];
    const float* image = (const float*)d_in[2];
    const float* Wq = (const float*)d_in[3];
    const float* Wk = (const float*)d_in[4];
    const float* Wv = (const float*)d_in[5];
    const float* Wp = (const float*)d_in[6];
    const float* bq = (const float*)d_in[7];
    const float* bk = (const float*)d_in[8];
    const float* bv = (const float*)d_in[9];
    const float* bp = (const float*)d_in[10];
    const float* qn = (const float*)d_in[11];
    const float* kn = (const float*)d_in[12];
    const float* rpb = (const float*)d_in[13];
    const float* Wg1 = (const float*)d_in[14];
    const float* bg1 = (const float*)d_in[15];
    const float* Wg2 = (const float*)d_in[16];
    const float* bg2 = (const float*)d_in[17];
    float* out = (float*)d_out;

    cudaFuncSetAttribute(tgemm_k<0>, cudaFuncAttributeMaxDynamicSharedMemorySize, GSMEMB);
    cudaFuncSetAttribute(tgemm_k<2>, cudaFuncAttributeMaxDynamicSharedMemorySize, GSMEMB);
    cudaFuncSetAttribute(tgemm_k<3>, cudaFuncAttributeMaxDynamicSharedMemorySize, GSMEMB);
    cudaFuncSetAttribute(attn_mma_k, cudaFuncAttributeMaxDynamicSharedMemorySize, ASMEM);

    dim3 blk(256), blkG(512);

    conv_k<<<dim3(2048, 3), blk>>>(audio, video, image);
    transW_k<<<dim3(32, 32, 12), blk>>>(Wq, Wk, Wv, Wp);
    transG_k<<<dim3(64, 96), blk>>>(Wg1);

    // QKV fused: bx 0-7 Q, 8-15 K, 16-23 V; by = j*16 + mtile
    tgemm_k<0><<<dim3(24, 48), blkG, GSMEMB>>>(bq, bk, bv, qn, kn, DD);
    attn_mma_k<<<dim3(384, 2), blkG, ASMEM>>>(rpb);
    tgemm_k<2><<<dim3(8, 48), blkG, GSMEMB>>>(bp, audio, video, image, nullptr, DD);
    tgemm_k<3><<<dim3(16, 16), blkG, GSMEMB>>>(bg1, nullptr, nullptr, nullptr, nullptr, K3D);
    gate_fuse_k<<<BTLR, 256>>>(Wg2, bg2, out);
}

// round 16
// speedup vs baseline: 1.0231x; 1.0231x over previous
#include <cuda_runtime.h>
#include <cuda_fp16.h>
#include <math.h>
#include <stdint.h>

#define BB 2
#define TT 32
#define LLE 64
#define DD 1024
#define HH 16
#define HD 64
#define NWIN 8
#define SSQ 512
#define AROWS 4096
#define TLTOK 2048
#define BTLR 4096
#define DG 2048
#define K3D 3072
#define FEATSZ ((size_t)BTLR * DD)
#define QSPAN ((size_t)NWIN * HH * SSQ * HD)

// GEMM smem (u32): A 2 ktiles x 256 rows x 12, B 2 ktiles x 128 x 12, x2 buf
#define AKT 3072
#define ABUF (2 * AKT)
#define BKT 1536
#define BBUF (2 * BKT)
#define BOFFU (2 * ABUF)
#define GSMEMB ((BOFFU + 2 * BBUF) * 4)   // 73728 B
// attn smem: QP 128x36 + 2 x (K 64x36 + V 64x36)
#define KVBUF (2 * 64 * 36)               // 4608 u32 per buffer (K+V)
#define ASMEM ((128 * 36 + 2 * KVBUF) * 4)   // 55296 B

__device__ __half g_Q[3 * QSPAN];
__device__ __half g_K[3 * QSPAN];
__device__ __half g_Vt[3 * QSPAN];                      // [j][bh][d][s]
__device__ __half g_Oh[(size_t)3 * AROWS * DD];
__device__ __half g_Xh[(size_t)3 * BTLR * DD];          // fp16 modalities
__device__ __half g_featsh[(size_t)3 * BTLR * DD];
__device__ __half g_Gh[(size_t)BTLR * DG];
__device__ __half g_Wh[(size_t)12 * DD * DD + (size_t)DG * K3D];

__device__ __forceinline__ float gelu_f(float x) {
    return 0.5f * x * (1.0f + erff(x * 0.70710678118654752440f));
}
__device__ __forceinline__ uint32_t pack2(float lo, float hi) {
    uint32_t u;
    asm("cvt.rn.f16x2.f32 %0, %1, %2;" : "=r"(u) : "f"(hi), "f"(lo));
    return u;
}
__device__ __forceinline__ uint32_t smem_u32(const void* p) {
    uint32_t a;
    asm("{ .reg .u64 t; cvta.to.shared.u64 t, %1; cvt.u32.u64 %0, t; }" : "=r"(a) : "l"(p));
    return a;
}
__device__ __forceinline__ void ldsm4(uint32_t* r, uint32_t sa) {
    asm volatile("ldmatrix.sync.aligned.m8n8.x4.shared.b16 {%0,%1,%2,%3}, [%4];"
        : "=r"(r[0]), "=r"(r[1]), "=r"(r[2]), "=r"(r[3]) : "r"(sa));
}
__device__ __forceinline__ void mma16(float* d, const uint32_t* a, const uint32_t* b) {
    asm volatile("mma.sync.aligned.m16n8k16.row.col.f32.f16.f16.f32 "
        "{%0,%1,%2,%3}, {%4,%5,%6,%7}, {%8,%9}, {%0,%1,%2,%3};"
        : "+f"(d[0]), "+f"(d[1]), "+f"(d[2]), "+f"(d[3])
        : "r"(a[0]), "r"(a[1]), "r"(a[2]), "r"(a[3]), "r"(b[0]), "r"(b[1]));
}

// ---------------- prepass: modalities fp32 -> fp16 ----------------
__global__ __launch_bounds__(256) void conv_k(
    const float* __restrict__ a, const float* __restrict__ v,
    const float* __restrict__ im)
{
    const float* src = (blockIdx.y == 0) ? a : (blockIdx.y == 1) ? v : im;
    __half* dst = g_Xh + (size_t)blockIdx.y * FEATSZ;
    const size_t i = ((size_t)blockIdx.x * 256 + threadIdx.x) * 8;
    float4 f0 = *(const float4*)(src + i);
    float4 f1 = *(const float4*)(src + i + 4);
    uint4 o = make_uint4(pack2(f0.x, f0.y), pack2(f0.z, f0.w),
                         pack2(f1.x, f1.y), pack2(f1.z, f1.w));
    *(uint4*)(dst + i) = o;
}

// ---------------- weight transposes -> fp16 [n][k] ----------------
__global__ __launch_bounds__(256) void transW_k(
    const float* __restrict__ Wq, const float* __restrict__ Wk,
    const float* __restrict__ Wv, const float* __restrict__ Wp)
{
    __shared__ float tile[32][33];
    const int z = blockIdx.z;
    const float* W = (z < 3) ? Wq + (size_t)z * DD * DD
                   : (z < 6) ? Wk + (size_t)(z - 3) * DD * DD
                   : (z < 9) ? Wv + (size_t)(z - 6) * DD * DD
                             : Wp + (size_t)(z - 9) * DD * DD;
    __half* Wt = g_Wh + (size_t)z * DD * DD;
    const int n0 = blockIdx.x << 5, k0 = blockIdx.y << 5;
    const int tx = threadIdx.x & 31, ty = threadIdx.x >> 5;
    #pragma unroll
    for (int j = 0; j < 32; j += 8)
        tile[ty + j][tx] = W[(size_t)(k0 + ty + j) * DD + n0 + tx];
    __syncthreads();
    const int tp = threadIdx.x & 15, nr = threadIdx.x >> 4;
    #pragma unroll
    for (int j = 0; j < 2; j++) {
        const int nn = nr + j * 16;
        __half2 hv = __floats2half2_rn(tile[2 * tp][nn], tile[2 * tp + 1][nn]);
        *(__half2*)(Wt + (size_t)(n0 + nn) * DD + k0 + 2 * tp) = hv;
    }
}
__global__ __launch_bounds__(256) void transG_k(const float* __restrict__ Wg1)
{
    __shared__ float tile[32][33];
    __half* Wt = g_Wh + (size_t)12 * DD * DD;
    const int n0 = blockIdx.x << 5, k0 = blockIdx.y << 5;
    const int tx = threadIdx.x & 31, ty = threadIdx.x >> 5;
    #pragma unroll
    for (int j = 0; j < 32; j += 8)
        tile[ty + j][tx] = Wg1[(size_t)(k0 + ty + j) * DG + n0 + tx];
    __syncthreads();
    const int tp = threadIdx.x & 15, nr = threadIdx.x >> 4;
    #pragma unroll
    for (int j = 0; j < 2; j++) {
        const int nn = nr + j * 16;
        __half2 hv = __floats2half2_rn(tile[2 * tp][nn], tile[2 * tp + 1][nn]);
        *(__half2*)(Wt + (size_t)(n0 + nn) * K3D + k0 + 2 * tp) = hv;
    }
}

// ---------------------------------------------------------------------------
// fp16 mma GEMM: CTA 256x128, 512 threads, 16 warps (8m x 2n), warp 32x64,
// K-chunk 32 (2 ktiles), double-buffered (R11 core).
// MODE 0 = QKV fused (grid (24,48): bx>>3 = 0 Q,1 K,2 V)
// MODE 2 = out-proj (grid (8,48));  MODE 3 = gate L1 (grid (16,16)).
// ---------------------------------------------------------------------------
template<int MODE>
__global__ __launch_bounds__(512) void tgemm_k(
    const float* __restrict__ p0, const float* __restrict__ p1,
    const float* __restrict__ p2, const float* __restrict__ p3,
    const float* __restrict__ p4, int K)
{
    extern __shared__ uint32_t smu[];
    const uint32_t sb = smem_u32(smu);

    const int tid = threadIdx.x;
    const int wid = tid >> 5, ln = tid & 31;
    const int warpm = wid & 7, warpn = wid >> 3;
    const int g = ln >> 2, t = ln & 3;

    int j, m0, n0, qkv = 0;
    if (MODE == 3) { j = 0; m0 = blockIdx.y << 8; n0 = blockIdx.x << 7; }
    else {
        j = blockIdx.y >> 4; m0 = (blockIdx.y & 15) << 8;
        if (MODE == 0) { qkv = blockIdx.x >> 3; n0 = (blockIdx.x & 7) << 7; }
        else           { n0 = blockIdx.x << 7; }
    }

    // staging geometry
    const int arowS = tid >> 1, ktA = tid & 1;
    const int browS = tid >> 2, ktB = (tid >> 1) & 1, hbB = tid & 1;

    // ldmatrix per-lane offsets (bytes, within one ktile buffer)
    const int arow_l = ((ln >> 3) & 1) * 8 + (ln & 7);
    const int akh = ln >> 4;
    int aoff[2];
    #pragma unroll
    for (int mi = 0; mi < 2; mi++)
        aoff[mi] = (((warpm * 32 + mi * 16 + arow_l) * 12) + akh * 4) << 2;
    const int brow_l = ((ln >> 4) * 8) + (ln & 7);
    const int bkh = (ln >> 3) & 1;
    int boff[4];
    #pragma unroll
    for (int pi = 0; pi < 4; pi++)
        boff[pi] = (((warpn * 64 + pi * 16 + brow_l) * 12) + bkh * 4) << 2;

    // A pointer
    const __half* Am;
    size_t arow;
    {
        const int ksl = (j == 1) ? 0 : 1;   // kv input: video,audio,video
        if (MODE == 0) {
            const int r = m0 + arowS;
            const int bw = r >> 9, s = r & 511;
            const int b = bw >> 2, w = bw & 3;
            const int st = s >> 6, l = s & 63;
            const int tt = (w * 8 + st + 4) & 31;    // roll(-SH) gather
            arow = (size_t)((b * TT + tt) * LLE + l) << 10;
            Am = g_Xh + (size_t)((qkv == 0) ? j : ksl) * FEATSZ;
        } else if (MODE == 2) {
            arow = (size_t)(m0 + arowS) << 10;
            Am = g_Oh + (size_t)j * AROWS * DD;
        } else {
            arow = (size_t)(m0 + arowS) << 10;
            Am = g_featsh;
        }
    }
    // B pointer
    size_t wh_off;
    if (MODE == 0)      wh_off = (size_t)(qkv * 3 + j) * DD * DD;
    else if (MODE == 2) wh_off = (size_t)(9 + j) * DD * DD;
    else                wh_off = (size_t)12 * DD * DD;
    const __half* Bw = g_Wh + wh_off + (size_t)(n0 + browS) * K + ktB * 16 + hbB * 8;

    uint4 pa[2], pb;
#define LOADG(kc) do {                                                            \
    const __half* as_;                                                            \
    if (MODE == 3) {                                                              \
        const int kg_ = (kc) + ktA * 16;                                          \
        as_ = g_featsh + (size_t)(kg_ >> 10) * FEATSZ + arow + (kg_ & 1023);      \
    } else {                                                                      \
        as_ = Am + arow + (kc) + ktA * 16;                                        \
    }                                                                             \
    pa[0] = *(const uint4*)(as_);                                                 \
    pa[1] = *(const uint4*)(as_ + 8);                                             \
    pb = *(const uint4*)(Bw + (kc));                                              \
} while (0)
#define STOREG(bf_) do {                                                          \
    uint32_t* a0_ = smu + (bf_) * ABUF + ktA * AKT + arowS * 12;                  \
    *(uint4*)a0_ = pa[0]; *(uint4*)(a0_ + 4) = pa[1];                             \
    uint32_t* b0_ = smu + BOFFU + (bf_) * BBUF + ktB * BKT + browS * 12 + hbB * 4;\
    *(uint4*)b0_ = pb;                                                            \
} while (0)

    float acc[2][8][4];
    #pragma unroll
    for (int i = 0; i < 2; i++)
        #pragma unroll
        for (int jj = 0; jj < 8; jj++)
            #pragma unroll
            for (int q = 0; q < 4; q++) acc[i][jj][q] = 0.f;

    const int NC = K >> 5;
    LOADG(0);
    STOREG(0);
    __syncthreads();

    for (int c = 0; c < NC; c++) {
        if (c + 1 < NC) LOADG((c + 1) << 5);
        const int bsel = c & 1;
        #pragma unroll
        for (int kt = 0; kt < 2; kt++) {
            const uint32_t ab = sb + ((bsel * ABUF + kt * AKT) << 2);
            const uint32_t bb = sb + ((BOFFU + bsel * BBUF + kt * BKT) << 2);
            uint32_t af[2][4], bfr[4][4];
            #pragma unroll
            for (int mi = 0; mi < 2; mi++)
                ldsm4(af[mi], ab + aoff[mi]);
            #pragma unroll
            for (int pi = 0; pi < 4; pi++)
                ldsm4(bfr[pi], bb + boff[pi]);
            #pragma unroll
            for (int mi = 0; mi < 2; mi++)
                #pragma unroll
                for (int ni = 0; ni < 8; ni++)
                    mma16(acc[mi][ni], af[mi], &bfr[ni >> 1][(ni & 1) * 2]);
        }
        if (c + 1 < NC) STOREG((c + 1) & 1);
        __syncthreads();
    }

    // ---- epilogue ----
    const float* bias =
        (MODE == 0) ? ((qkv == 0) ? p0 : (qkv == 1) ? p1 : p2) + j * DD :
        (MODE == 2) ? p0 + j * DD : p0;
    const float* nw =
        (MODE == 0 && qkv == 0) ? p3 + j * HD :
        (MODE == 0 && qkv == 1) ? p4 + j * HD : nullptr;
    const float nscale = (MODE == 0 && qkv == 0) ? 0.125f : 1.0f;

    float2 bz[8], nz[8];
    #pragma unroll
    for (int ni = 0; ni < 8; ni++)
        bz[ni] = *(const float2*)(bias + n0 + warpn * 64 + ni * 8 + 2 * t);
    if (nw) {
        #pragma unroll
        for (int ni = 0; ni < 8; ni++)
            nz[ni] = *(const float2*)(nw + ni * 8 + 2 * t);
    }

    #pragma unroll
    for (int mi = 0; mi < 2; mi++)
    #pragma unroll
    for (int rh = 0; rh < 2; rh++) {
        const int m = m0 + warpm * 32 + mi * 16 + rh * 8 + g;
        float v[16];
        #pragma unroll
        for (int ni = 0; ni < 8; ni++) {
            v[2*ni]   = acc[mi][ni][2*rh]   + bz[ni].x;
            v[2*ni+1] = acc[mi][ni][2*rh+1] + bz[ni].y;
        }
        if (MODE == 0) {
            const int bw = m >> 9, s = m & 511;
            const int h = (n0 + warpn * 64) >> 6;
            if (nw) {
                float ss = 0.f;
                #pragma unroll
                for (int jj = 0; jj < 16; jj++) ss = fmaf(v[jj], v[jj], ss);
                ss += __shfl_xor_sync(0xffffffffu, ss, 1);
                ss += __shfl_xor_sync(0xffffffffu, ss, 2);
                const float rs = rsqrtf(ss * (1.f / 64.f) + 1e-6f) * nscale;
                #pragma unroll
                for (int ni = 0; ni < 8; ni++) {
                    v[2*ni]   *= rs * nz[ni].x;
                    v[2*ni+1] *= rs * nz[ni].y;
                }
            }
            if (qkv == 2) {                 // V: transposed fp16 store
                __half* Vb = g_Vt + (size_t)j * QSPAN;
                #pragma unroll
                for (int ni = 0; ni < 8; ni++) {
                    const int d = ni * 8 + 2 * t;
                    size_t base = (((size_t)(bw * HH + h) * 64 + d) << 9) + s;
                    Vb[base]       = __float2half_rn(v[2*ni]);
                    Vb[base + 512] = __float2half_rn(v[2*ni+1]);
                }
            } else {
                uint32_t* Cp = (uint32_t*)((qkv == 0) ? (g_Q + (size_t)j * QSPAN)
                                                      : (g_K + (size_t)j * QSPAN));
                const size_t rowb = (((size_t)(bw * HH + h) * 512 + s)) * 32;
                #pragma unroll
                for (int ni = 0; ni < 8; ni++)
                    Cp[rowb + ni * 4 + t] = pack2(v[2*ni], v[2*ni+1]);
            }
        } else if (MODE == 2) {
            const int bw = m >> 9, s = m & 511;
            const int b = bw >> 2, w = bw & 3;
            const int st = s >> 6, l = s & 63;
            const int tg = (w * 8 + st + 4) & 31;    // roll(+SH) scatter
            const size_t rowo = ((size_t)(b * TLTOK + tg * LLE + l) << 10)
                              + n0 + warpn * 64 + 2 * t;
            const float* rbase = (j == 0) ? p1 : (j == 1) ? p2 : p3;
            const float* rr = rbase + ((size_t)((b * TT + tg) * LLE + l) << 10)
                            + n0 + warpn * 64 + 2 * t;
            uint32_t* fh = (uint32_t*)(g_featsh + (size_t)j * FEATSZ + rowo);
            #pragma unroll
            for (int ni = 0; ni < 8; ni++) {
                float2 r2 = *(const float2*)(rr + ni * 8);
                fh[ni * 4] = pack2(v[2*ni] + r2.x, v[2*ni+1] + r2.y);
            }
        } else {
            uint32_t* gp = (uint32_t*)(g_Gh + (size_t)m * DG + n0 + warpn * 64 + 2 * t);
            #pragma unroll
            for (int ni = 0; ni < 8; ni++)
                gp[ni * 4] = pack2(gelu_f(v[2*ni]), gelu_f(v[2*ni+1]));
        }
    }
}

// ---------------------------------------------------------------------------
// Flash attention (R14): 256 threads, 128 q-rows, 2 CTA/SM, double-buffered
// K/V staging with register prefetch (1 barrier per K-tile).
// ---------------------------------------------------------------------------
__global__ __launch_bounds__(256, 2) void attn_mma_k(const float* __restrict__ rpb0)
{
    extern __shared__ uint32_t sma[];
    uint32_t* QP = sma;                       // 128*36
    const uint32_t sa0 = smem_u32(sma);
    const uint32_t qb_sa = sa0;

    const int tid = threadIdx.x;
    const int wid = tid >> 5, ln = tid & 31;
    const int g = ln >> 2, t = ln & 3;
    const int j = blockIdx.x >> 7, bhl = blockIdx.x & 127;
    const int qt = blockIdx.y;
    const int h = bhl & 15, bw = bhl >> 4;
    const int q0 = qt << 7;
    const int tq = (qt << 1) + (wid >> 2);
    const int mrow = wid << 4;
    const float* rpb = rpb0 + j * 15 * HH;

    const uint32_t* Qb  = (const uint32_t*)(g_Q  + (size_t)j * QSPAN);
    const uint32_t* Kb  = (const uint32_t*)(g_K  + (size_t)j * QSPAN);
    const uint32_t* Vtb = (const uint32_t*)(g_Vt + (size_t)j * QSPAN);

    const int arow_l = ((ln >> 3) & 1) * 8 + (ln & 7);
    const int akh = ln >> 4;
    const int aoff = ((mrow + arow_l) * 36 + akh * 4) << 2;
    const int brow_l = ((ln >> 4) * 8) + (ln & 7);
    const int bkh = (ln >> 3) & 1;
    int boff[4];
    #pragma unroll
    for (int pi = 0; pi < 4; pi++)
        boff[pi] = ((pi * 16 + brow_l) * 36 + bkh * 4) << 2;

    {   // stage Q
        const int r = tid >> 1, cu = (tid & 1) << 4;
        const uint32_t* qs = Qb + ((size_t)(bhl * 512 + q0 + r)) * 32 + cu;
        #pragma unroll
        for (int u = 0; u < 4; u++)
            *(uint4*)&QP[r * 36 + cu + u * 4] = *(const uint4*)(qs + u * 4);
    }
    __syncthreads();

    uint32_t af[4][4];
    #pragma unroll
    for (int kt4 = 0; kt4 < 4; kt4++)
        ldsm4(af[kt4], qb_sa + aoff + (kt4 << 5));
    __syncthreads();

    float oc[8][4];
    #pragma unroll
    for (int i = 0; i < 8; i++)
        #pragma unroll
        for (int q = 0; q < 4; q++) oc[i][q] = 0.f;
    float m_i[2] = {-1e30f, -1e30f}, l_i[2] = {0.f, 0.f};

    const int sr = tid >> 2, scu = (tid & 3) << 3;

    uint4 pk[2], pv[2];
#define LOADKV(kt_) do {                                                          \
    const uint32_t* ks_ = Kb + ((size_t)(bhl * 512 + (kt_) * 64 + sr)) * 32 + scu;\
    pk[0] = *(const uint4*)ks_;                                                   \
    pk[1] = *(const uint4*)(ks_ + 4);                                             \
    const uint32_t* vs_ = Vtb + ((size_t)(bhl * 64 + sr)) * 256 + (kt_) * 32 + scu;\
    pv[0] = *(const uint4*)vs_;                                                   \
    pv[1] = *(const uint4*)(vs_ + 4);                                             \
} while (0)

    LOADKV(0);

    for (int kt = 0; kt < 8; kt++) {
        const float bias_s = rpb[(tq - kt + 7) * HH + h];
        const int buf = kt & 1;
        uint32_t* Ktb  = sma + 128 * 36 + buf * KVBUF;
        uint32_t* Vtbs = Ktb + 64 * 36;
        *(uint4*)&Ktb[sr * 36 + scu]      = pk[0];
        *(uint4*)&Ktb[sr * 36 + scu + 4]  = pk[1];
        *(uint4*)&Vtbs[sr * 36 + scu]     = pv[0];
        *(uint4*)&Vtbs[sr * 36 + scu + 4] = pv[1];
        __syncthreads();
        if (kt < 7) LOADKV(kt + 1);
        const uint32_t kb_sa = sa0 + ((128 * 36 + buf * KVBUF) << 2);
        const uint32_t vb_sa = kb_sa + (64 * 36 << 2);

        float sc[8][4];
        #pragma unroll
        for (int i = 0; i < 8; i++)
            #pragma unroll
            for (int q = 0; q < 4; q++) sc[i][q] = 0.f;
        #pragma unroll
        for (int kt4 = 0; kt4 < 4; kt4++) {
            uint32_t bfr[4][4];
            #pragma unroll
            for (int pi = 0; pi < 4; pi++)
                ldsm4(bfr[pi], kb_sa + boff[pi] + (kt4 << 5));
            #pragma unroll
            for (int ni = 0; ni < 8; ni++)
                mma16(sc[ni], af[kt4], &bfr[ni >> 1][(ni & 1) * 2]);
        }

        #pragma unroll
        for (int hr = 0; hr < 2; hr++) {
            float mx = -1e30f;
            #pragma unroll
            for (int ni = 0; ni < 8; ni++)
                mx = fmaxf(mx, fmaxf(sc[ni][2*hr], sc[ni][2*hr+1]));
            mx += bias_s;
            mx = fmaxf(mx, __shfl_xor_sync(0xffffffffu, mx, 1));
            mx = fmaxf(mx, __shfl_xor_sync(0xffffffffu, mx, 2));
            const float mn = fmaxf(m_i[hr], mx);
            const float fac = __expf(m_i[hr] - mn);
            m_i[hr] = mn;
            float sum = 0.f;
            const int prow = (mrow + hr * 8 + g) * 36;
            #pragma unroll
            for (int ni = 0; ni < 8; ni++) {
                float p0 = __expf(sc[ni][2*hr]   + bias_s - mn);
                float p1 = __expf(sc[ni][2*hr+1] + bias_s - mn);
                sum += p0 + p1;
                QP[prow + ni * 4 + t] = pack2(p0, p1);
            }
            sum += __shfl_xor_sync(0xffffffffu, sum, 1);
            sum += __shfl_xor_sync(0xffffffffu, sum, 2);
            l_i[hr] = l_i[hr] * fac + sum;
            #pragma unroll
            for (int ni = 0; ni < 8; ni++) {
                oc[ni][2*hr]   *= fac;
                oc[ni][2*hr+1] *= fac;
            }
        }
        __syncwarp();   // P is warp-private

        #pragma unroll
        for (int kp = 0; kp < 4; kp++) {
            uint32_t pf[4], vfr[4][4];
            ldsm4(pf, qb_sa + aoff + (kp << 5));
            #pragma unroll
            for (int pi = 0; pi < 4; pi++)
                ldsm4(vfr[pi], vb_sa + boff[pi] + (kp << 5));
            #pragma unroll
            for (int ni = 0; ni < 8; ni++)
                mma16(oc[ni], pf, &vfr[ni >> 1][(ni & 1) * 2]);
        }
    }

    const float inv0 = 1.0f / l_i[0], inv1 = 1.0f / l_i[1];
    #pragma unroll
    for (int hr = 0; hr < 2; hr++) {
        const float inv = hr ? inv1 : inv0;
        const int row = q0 + mrow + hr * 8 + g;
        uint32_t* dst = (uint32_t*)g_Oh
            + ((size_t)j * AROWS + bw * SSQ + row) * 512 + h * 32 + t;
        #pragma unroll
        for (int ni = 0; ni < 8; ni++)
            dst[ni * 4] = pack2(oc[ni][2*hr] * inv, oc[ni][2*hr+1] * inv);
    }
}

// ---------------------------------------------------------------------------
// Gate logits (fp16 G) + softmax + fuse (fp16 feats).
// ---------------------------------------------------------------------------
__global__ __launch_bounds__(256) void gate_fuse_k(const float* __restrict__ Wg2,
                                                   const float* __restrict__ bg2,
                                                   float* __restrict__ out)
{
    const int row = blockIdx.x, tid = threadIdx.x;
    const __half2* gh = (const __half2*)(g_Gh + (size_t)row * DG);
    float s0 = 0.f, s1 = 0.f, s2 = 0.f;
    for (int kp = tid; kp < DG / 2; kp += 256) {
        float2 x2 = __half22float2(gh[kp]);
        const int k = kp * 2;
        s0 = fmaf(x2.x, Wg2[k*3+0], fmaf(x2.y, Wg2[k*3+3], s0));
        s1 = fmaf(x2.x, Wg2[k*3+1], fmaf(x2.y, Wg2[k*3+4], s1));
        s2 = fmaf(x2.x, Wg2[k*3+2], fmaf(x2.y, Wg2[k*3+5], s2));
    }
    #pragma unroll
    for (int m = 16; m; m >>= 1) {
        s0 += __shfl_xor_sync(0xffffffffu, s0, m);
        s1 += __shfl_xor_sync(0xffffffffu, s1, m);
        s2 += __shfl_xor_sync(0xffffffffu, s2, m);
    }
    __shared__ float red[3][8];
    __shared__ float gl[3];
    int wid = tid >> 5, lane = tid & 31;
    if (lane == 0) { red[0][wid]=s0; red[1][wid]=s1; red[2][wid]=s2; }
    __syncthreads();
    if (tid < 3) {
        float s = bg2[tid];
        #pragma unroll
        for (int w = 0; w < 8; w++) s += red[tid][w];
        gl[tid] = s;
    }
    __syncthreads();
    float a0 = gl[0], a1 = gl[1], a2 = gl[2];
    float mx = fmaxf(a0, fmaxf(a1, a2));
    float e0 = __expf(a0-mx), e1 = __expf(a1-mx), e2 = __expf(a2-mx);
    float inv = 1.0f / (e0 + e1 + e2);
    e0 *= inv; e1 *= inv; e2 *= inv;
    const uint2* f0 = (const uint2*)(g_featsh + (size_t)0*FEATSZ + (size_t)row*DD);
    const uint2* f1 = (const uint2*)(g_featsh + (size_t)1*FEATSZ + (size_t)row*DD);
    const uint2* f2 = (const uint2*)(g_featsh + (size_t)2*FEATSZ + (size_t)row*DD);
    float4* o4 = (float4*)(out + (size_t)row * DD);
    uint2 u0 = f0[tid], u1 = f1[tid], u2 = f2[tid];
    float2 a_0 = __half22float2(*(__half2*)&u0.x), a_1 = __half22float2(*(__half2*)&u0.y);
    float2 b_0 = __half22float2(*(__half2*)&u1.x), b_1 = __half22float2(*(__half2*)&u1.y);
    float2 c_0 = __half22float2(*(__half2*)&u2.x), c_1 = __half22float2(*(__half2*)&u2.y);
    o4[tid] = make_float4(e0*a_0.x + e1*b_0.x + e2*c_0.x,
                          e0*a_0.y + e1*b_0.y + e2*c_0.y,
                          e0*a_1.x + e1*b_1.x + e2*c_1.x,
                          e0*a_1.y + e1*b_1.y + e2*c_1.y);
}

// ---------------------------------------------------------------------------
// Launch (stream fork/join: transW+transG overlap conv; join before QKV/gate)
// ---------------------------------------------------------------------------
extern "C" void kernel_launch(void* const* d_in, const int* in_sizes, int n_in,
                              void* d_out, int out_size)
{
    const float* audio = (const float*)d_in[0];
    const float* video = (const float*)d_in[1];
    const float* image = (const float*)d_in[2];
    const float* Wq = (const float*)d_in[3];
    const float* Wk = (const float*)d_in[4];
    const float* Wv = (const float*)d_in[5];
    const float* Wp = (const float*)d_in[6];
    const float* bq = (const float*)d_in[7];
    const float* bk = (const float*)d_in[8];
    const float* bv = (const float*)d_in[9];
    const float* bp = (const float*)d_in[10];
    const float* qn = (const float*)d_in[11];
    const float* kn = (const float*)d_in[12];
    const float* rpb = (const float*)d_in[13];
    const float* Wg1 = (const float*)d_in[14];
    const float* bg1 = (const float*)d_in[15];
    const float* Wg2 = (const float*)d_in[16];
    const float* bg2 = (const float*)d_in[17];
    float* out = (float*)d_out;

    static int init_done = 0;
    static cudaStream_t s2;
    static cudaEvent_t ev0, evW, evG;
    if (!init_done) {
        cudaStreamCreateWithFlags(&s2, cudaStreamNonBlocking);
        cudaEventCreateWithFlags(&ev0, cudaEventDisableTiming);
        cudaEventCreateWithFlags(&evW, cudaEventDisableTiming);
        cudaEventCreateWithFlags(&evG, cudaEventDisableTiming);
        cudaFuncSetAttribute(tgemm_k<0>, cudaFuncAttributeMaxDynamicSharedMemorySize, GSMEMB);
        cudaFuncSetAttribute(tgemm_k<2>, cudaFuncAttributeMaxDynamicSharedMemorySize, GSMEMB);
        cudaFuncSetAttribute(tgemm_k<3>, cudaFuncAttributeMaxDynamicSharedMemorySize, GSMEMB);
        cudaFuncSetAttribute(attn_mma_k, cudaFuncAttributeMaxDynamicSharedMemorySize, ASMEM);
        init_done = 1;
    }

    dim3 blk(256), blkG(512);

    // fork: s2 does weight transposes while main does activation conversion
    cudaEventRecord(ev0, 0);
    cudaStreamWaitEvent(s2, ev0, 0);
    transW_k<<<dim3(32, 32, 12), blk, 0, s2>>>(Wq, Wk, Wv, Wp);
    cudaEventRecord(evW, s2);
    transG_k<<<dim3(64, 96), blk, 0, s2>>>(Wg1);
    cudaEventRecord(evG, s2);

    conv_k<<<dim3(2048, 3), blk>>>(audio, video, image);

    // join for QKV (needs conv + transW)
    cudaStreamWaitEvent(0, evW, 0);
    tgemm_k<0><<<dim3(24, 48), blkG, GSMEMB>>>(bq, bk, bv, qn, kn, DD);
    attn_mma_k<<<dim3(384, 4), blk, ASMEM>>>(rpb);
    tgemm_k<2><<<dim3(8, 48), blkG, GSMEMB>>>(bp, audio, video, image, nullptr, DD);
    // join for gate L1 (needs transG)
    cudaStreamWaitEvent(0, evG, 0);
    tgemm_k<3><<<dim3(16, 16), blkG, GSMEMB>>>(bg1, nullptr, nullptr, nullptr, nullptr, K3D);
    gate_fuse_k<<<BTLR, 256>>>(Wg2, bg2, out);
}

// round 17
// speedup vs baseline: 1.0580x; 1.0340x over previous
#include <cuda_runtime.h>
#include <cuda_fp16.h>
#include <math.h>
#include <stdint.h>

#define BB 2
#define TT 32
#define LLE 64
#define DD 1024
#define HH 16
#define HD 64
#define NWIN 8
#define SSQ 512
#define AROWS 4096
#define TLTOK 2048
#define BTLR 4096
#define DG 2048
#define K3D 3072
#define FEATSZ ((size_t)BTLR * DD)
#define QSPAN ((size_t)NWIN * HH * SSQ * HD)

#define AKT 3072
#define ABUF (2 * AKT)
#define BKT 1536
#define BBUF (2 * BKT)
#define BOFFU (2 * ABUF)
#define GSMEMB ((BOFFU + 2 * BBUF) * 4)   // 73728 B
#define KVBUF (2 * 64 * 36)
#define ASMEM ((128 * 36 + 2 * KVBUF) * 4)   // 55296 B

__device__ __half g_Q[3 * QSPAN];
__device__ __half g_K[3 * QSPAN];
__device__ __half g_Vt[3 * QSPAN];
__device__ __half g_Oh[(size_t)3 * AROWS * DD];
__device__ __half g_Xh[(size_t)3 * BTLR * DD];
__device__ __half g_featsh[(size_t)3 * BTLR * DD];
__device__ __half g_Gh[(size_t)BTLR * DG];
__device__ __half g_Wh[(size_t)12 * DD * DD + (size_t)DG * K3D];

__device__ __forceinline__ float gelu_f(float x) {
    return 0.5f * x * (1.0f + erff(x * 0.70710678118654752440f));
}
__device__ __forceinline__ uint32_t pack2(float lo, float hi) {
    uint32_t u;
    asm("cvt.rn.f16x2.f32 %0, %1, %2;" : "=r"(u) : "f"(hi), "f"(lo));
    return u;
}
__device__ __forceinline__ uint32_t smem_u32(const void* p) {
    uint32_t a;
    asm("{ .reg .u64 t; cvta.to.shared.u64 t, %1; cvt.u32.u64 %0, t; }" : "=r"(a) : "l"(p));
    return a;
}
__device__ __forceinline__ void ldsm4(uint32_t* r, uint32_t sa) {
    asm volatile("ldmatrix.sync.aligned.m8n8.x4.shared.b16 {%0,%1,%2,%3}, [%4];"
        : "=r"(r[0]), "=r"(r[1]), "=r"(r[2]), "=r"(r[3]) : "r"(sa));
}
__device__ __forceinline__ void mma16(float* d, const uint32_t* a, const uint32_t* b) {
    asm volatile("mma.sync.aligned.m16n8k16.row.col.f32.f16.f16.f32 "
        "{%0,%1,%2,%3}, {%4,%5,%6,%7}, {%8,%9}, {%0,%1,%2,%3};"
        : "+f"(d[0]), "+f"(d[1]), "+f"(d[2]), "+f"(d[3])
        : "r"(a[0]), "r"(a[1]), "r"(a[2]), "r"(a[3]), "r"(b[0]), "r"(b[1]));
}

// ---------------- prepass: modalities fp32 -> fp16 ----------------
__global__ __launch_bounds__(256) void conv_k(
    const float* __restrict__ a, const float* __restrict__ v,
    const float* __restrict__ im)
{
    const float* src = (blockIdx.y == 0) ? a : (blockIdx.y == 1) ? v : im;
    __half* dst = g_Xh + (size_t)blockIdx.y * FEATSZ;
    const size_t i = ((size_t)blockIdx.x * 256 + threadIdx.x) * 8;
    float4 f0 = *(const float4*)(src + i);
    float4 f1 = *(const float4*)(src + i + 4);
    uint4 o = make_uint4(pack2(f0.x, f0.y), pack2(f0.z, f0.w),
                         pack2(f1.x, f1.y), pack2(f1.z, f1.w));
    *(uint4*)(dst + i) = o;
}

// ---------------- weight transposes -> fp16 [n][k] ----------------
__global__ __launch_bounds__(256) void transW_k(
    const float* __restrict__ Wq, const float* __restrict__ Wk,
    const float* __restrict__ Wv, const float* __restrict__ Wp)
{
    __shared__ float tile[32][33];
    const int z = blockIdx.z;
    const float* W = (z < 3) ? Wq + (size_t)z * DD * DD
                   : (z < 6) ? Wk + (size_t)(z - 3) * DD * DD
                   : (z < 9) ? Wv + (size_t)(z - 6) * DD * DD
                             : Wp + (size_t)(z - 9) * DD * DD;
    __half* Wt = g_Wh + (size_t)z * DD * DD;
    const int n0 = blockIdx.x << 5, k0 = blockIdx.y << 5;
    const int tx = threadIdx.x & 31, ty = threadIdx.x >> 5;
    #pragma unroll
    for (int j = 0; j < 32; j += 8)
        tile[ty + j][tx] = W[(size_t)(k0 + ty + j) * DD + n0 + tx];
    __syncthreads();
    const int tp = threadIdx.x & 15, nr = threadIdx.x >> 4;
    #pragma unroll
    for (int j = 0; j < 2; j++) {
        const int nn = nr + j * 16;
        __half2 hv = __floats2half2_rn(tile[2 * tp][nn], tile[2 * tp + 1][nn]);
        *(__half2*)(Wt + (size_t)(n0 + nn) * DD + k0 + 2 * tp) = hv;
    }
}
__global__ __launch_bounds__(256) void transG_k(const float* __restrict__ Wg1)
{
    __shared__ float tile[32][33];
    __half* Wt = g_Wh + (size_t)12 * DD * DD;
    const int n0 = blockIdx.x << 5, k0 = blockIdx.y << 5;
    const int tx = threadIdx.x & 31, ty = threadIdx.x >> 5;
    #pragma unroll
    for (int j = 0; j < 32; j += 8)
        tile[ty + j][tx] = Wg1[(size_t)(k0 + ty + j) * DG + n0 + tx];
    __syncthreads();
    const int tp = threadIdx.x & 15, nr = threadIdx.x >> 4;
    #pragma unroll
    for (int j = 0; j < 2; j++) {
        const int nn = nr + j * 16;
        __half2 hv = __floats2half2_rn(tile[2 * tp][nn], tile[2 * tp + 1][nn]);
        *(__half2*)(Wt + (size_t)(n0 + nn) * K3D + k0 + 2 * tp) = hv;
    }
}

// ---------------------------------------------------------------------------
// fp16 mma GEMM (R11 core). j passed as parameter (per-modality streams).
// MODE 0 = QKV (grid (24,16): bx>>3 = 0 Q,1 K,2 V)
// MODE 2 = out-proj (grid (8,16));  MODE 3 = gate L1 (grid (16,16), jp=0).
// ---------------------------------------------------------------------------
template<int MODE>
__global__ __launch_bounds__(512) void tgemm_k(
    const float* __restrict__ p0, const float* __restrict__ p1,
    const float* __restrict__ p2, const float* __restrict__ p3,
    const float* __restrict__ p4, int jp, int K)
{
    extern __shared__ uint32_t smu[];
    const uint32_t sb = smem_u32(smu);

    const int tid = threadIdx.x;
    const int wid = tid >> 5, ln = tid & 31;
    const int warpm = wid & 7, warpn = wid >> 3;
    const int g = ln >> 2, t = ln & 3;

    const int j = jp;
    int m0, n0, qkv = 0;
    if (MODE == 3) { m0 = blockIdx.y << 8; n0 = blockIdx.x << 7; }
    else {
        m0 = blockIdx.y << 8;
        if (MODE == 0) { qkv = blockIdx.x >> 3; n0 = (blockIdx.x & 7) << 7; }
        else           { n0 = blockIdx.x << 7; }
    }

    const int arowS = tid >> 1, ktA = tid & 1;
    const int browS = tid >> 2, ktB = (tid >> 1) & 1, hbB = tid & 1;

    const int arow_l = ((ln >> 3) & 1) * 8 + (ln & 7);
    const int akh = ln >> 4;
    int aoff[2];
    #pragma unroll
    for (int mi = 0; mi < 2; mi++)
        aoff[mi] = (((warpm * 32 + mi * 16 + arow_l) * 12) + akh * 4) << 2;
    const int brow_l = ((ln >> 4) * 8) + (ln & 7);
    const int bkh = (ln >> 3) & 1;
    int boff[4];
    #pragma unroll
    for (int pi = 0; pi < 4; pi++)
        boff[pi] = (((warpn * 64 + pi * 16 + brow_l) * 12) + bkh * 4) << 2;

    const __half* Am;
    size_t arow;
    {
        const int ksl = (j == 1) ? 0 : 1;   // kv input: video,audio,video
        if (MODE == 0) {
            const int r = m0 + arowS;
            const int bw = r >> 9, s = r & 511;
            const int b = bw >> 2, w = bw & 3;
            const int st = s >> 6, l = s & 63;
            const int tt = (w * 8 + st + 4) & 31;    // roll(-SH) gather
            arow = (size_t)((b * TT + tt) * LLE + l) << 10;
            Am = g_Xh + (size_t)((qkv == 0) ? j : ksl) * FEATSZ;
        } else if (MODE == 2) {
            arow = (size_t)(m0 + arowS) << 10;
            Am = g_Oh + (size_t)j * AROWS * DD;
        } else {
            arow = (size_t)(m0 + arowS) << 10;
            Am = g_featsh;
        }
    }
    size_t wh_off;
    if (MODE == 0)      wh_off = (size_t)(qkv * 3 + j) * DD * DD;
    else if (MODE == 2) wh_off = (size_t)(9 + j) * DD * DD;
    else                wh_off = (size_t)12 * DD * DD;
    const __half* Bw = g_Wh + wh_off + (size_t)(n0 + browS) * K + ktB * 16 + hbB * 8;

    uint4 pa[2], pb;
#define LOADG(kc) do {                                                            \
    const __half* as_;                                                            \
    if (MODE == 3) {                                                              \
        const int kg_ = (kc) + ktA * 16;                                          \
        as_ = g_featsh + (size_t)(kg_ >> 10) * FEATSZ + arow + (kg_ & 1023);      \
    } else {                                                                      \
        as_ = Am + arow + (kc) + ktA * 16;                                        \
    }                                                                             \
    pa[0] = *(const uint4*)(as_);                                                 \
    pa[1] = *(const uint4*)(as_ + 8);                                             \
    pb = *(const uint4*)(Bw + (kc));                                              \
} while (0)
#define STOREG(bf_) do {                                                          \
    uint32_t* a0_ = smu + (bf_) * ABUF + ktA * AKT + arowS * 12;                  \
    *(uint4*)a0_ = pa[0]; *(uint4*)(a0_ + 4) = pa[1];                             \
    uint32_t* b0_ = smu + BOFFU + (bf_) * BBUF + ktB * BKT + browS * 12 + hbB * 4;\
    *(uint4*)b0_ = pb;                                                            \
} while (0)

    float acc[2][8][4];
    #pragma unroll
    for (int i = 0; i < 2; i++)
        #pragma unroll
        for (int jj = 0; jj < 8; jj++)
            #pragma unroll
            for (int q = 0; q < 4; q++) acc[i][jj][q] = 0.f;

    const int NC = K >> 5;
    LOADG(0);
    STOREG(0);
    __syncthreads();

    for (int c = 0; c < NC; c++) {
        if (c + 1 < NC) LOADG((c + 1) << 5);
        const int bsel = c & 1;
        #pragma unroll
        for (int kt = 0; kt < 2; kt++) {
            const uint32_t ab = sb + ((bsel * ABUF + kt * AKT) << 2);
            const uint32_t bb = sb + ((BOFFU + bsel * BBUF + kt * BKT) << 2);
            uint32_t af[2][4], bfr[4][4];
            #pragma unroll
            for (int mi = 0; mi < 2; mi++)
                ldsm4(af[mi], ab + aoff[mi]);
            #pragma unroll
            for (int pi = 0; pi < 4; pi++)
                ldsm4(bfr[pi], bb + boff[pi]);
            #pragma unroll
            for (int mi = 0; mi < 2; mi++)
                #pragma unroll
                for (int ni = 0; ni < 8; ni++)
                    mma16(acc[mi][ni], af[mi], &bfr[ni >> 1][(ni & 1) * 2]);
        }
        if (c + 1 < NC) STOREG((c + 1) & 1);
        __syncthreads();
    }

    // ---- epilogue ----
    const float* bias =
        (MODE == 0) ? ((qkv == 0) ? p0 : (qkv == 1) ? p1 : p2) + j * DD :
        (MODE == 2) ? p0 + j * DD : p0;
    const float* nw =
        (MODE == 0 && qkv == 0) ? p3 + j * HD :
        (MODE == 0 && qkv == 1) ? p4 + j * HD : nullptr;
    const float nscale = (MODE == 0 && qkv == 0) ? 0.125f : 1.0f;

    float2 bz[8], nz[8];
    #pragma unroll
    for (int ni = 0; ni < 8; ni++)
        bz[ni] = *(const float2*)(bias + n0 + warpn * 64 + ni * 8 + 2 * t);
    if (nw) {
        #pragma unroll
        for (int ni = 0; ni < 8; ni++)
            nz[ni] = *(const float2*)(nw + ni * 8 + 2 * t);
    }

    #pragma unroll
    for (int mi = 0; mi < 2; mi++)
    #pragma unroll
    for (int rh = 0; rh < 2; rh++) {
        const int m = m0 + warpm * 32 + mi * 16 + rh * 8 + g;
        float v[16];
        #pragma unroll
        for (int ni = 0; ni < 8; ni++) {
            v[2*ni]   = acc[mi][ni][2*rh]   + bz[ni].x;
            v[2*ni+1] = acc[mi][ni][2*rh+1] + bz[ni].y;
        }
        if (MODE == 0) {
            const int bw = m >> 9, s = m & 511;
            const int h = (n0 + warpn * 64) >> 6;
            if (nw) {
                float ss = 0.f;
                #pragma unroll
                for (int jj = 0; jj < 16; jj++) ss = fmaf(v[jj], v[jj], ss);
                ss += __shfl_xor_sync(0xffffffffu, ss, 1);
                ss += __shfl_xor_sync(0xffffffffu, ss, 2);
                const float rs = rsqrtf(ss * (1.f / 64.f) + 1e-6f) * nscale;
                #pragma unroll
                for (int ni = 0; ni < 8; ni++) {
                    v[2*ni]   *= rs * nz[ni].x;
                    v[2*ni+1] *= rs * nz[ni].y;
                }
            }
            if (qkv == 2) {                 // V: transposed fp16 store
                __half* Vb = g_Vt + (size_t)j * QSPAN;
                #pragma unroll
                for (int ni = 0; ni < 8; ni++) {
                    const int d = ni * 8 + 2 * t;
                    size_t base = (((size_t)(bw * HH + h) * 64 + d) << 9) + s;
                    Vb[base]       = __float2half_rn(v[2*ni]);
                    Vb[base + 512] = __float2half_rn(v[2*ni+1]);
                }
            } else {
                uint32_t* Cp = (uint32_t*)((qkv == 0) ? (g_Q + (size_t)j * QSPAN)
                                                      : (g_K + (size_t)j * QSPAN));
                const size_t rowb = (((size_t)(bw * HH + h) * 512 + s)) * 32;
                #pragma unroll
                for (int ni = 0; ni < 8; ni++)
                    Cp[rowb + ni * 4 + t] = pack2(v[2*ni], v[2*ni+1]);
            }
        } else if (MODE == 2) {
            const int bw = m >> 9, s = m & 511;
            const int b = bw >> 2, w = bw & 3;
            const int st = s >> 6, l = s & 63;
            const int tg = (w * 8 + st + 4) & 31;    // roll(+SH) scatter
            const size_t rowo = ((size_t)(b * TLTOK + tg * LLE + l) << 10)
                              + n0 + warpn * 64 + 2 * t;
            const float* rbase = (j == 0) ? p1 : (j == 1) ? p2 : p3;
            const float* rr = rbase + ((size_t)((b * TT + tg) * LLE + l) << 10)
                            + n0 + warpn * 64 + 2 * t;
            uint32_t* fh = (uint32_t*)(g_featsh + (size_t)j * FEATSZ + rowo);
            #pragma unroll
            for (int ni = 0; ni < 8; ni++) {
                float2 r2 = *(const float2*)(rr + ni * 8);
                fh[ni * 4] = pack2(v[2*ni] + r2.x, v[2*ni+1] + r2.y);
            }
        } else {
            uint32_t* gp = (uint32_t*)(g_Gh + (size_t)m * DG + n0 + warpn * 64 + 2 * t);
            #pragma unroll
            for (int ni = 0; ni < 8; ni++)
                gp[ni * 4] = pack2(gelu_f(v[2*ni]), gelu_f(v[2*ni+1]));
        }
    }
}

// ---------------------------------------------------------------------------
// Flash attention (R14 core), j as parameter; grid (128, 4).
// ---------------------------------------------------------------------------
__global__ __launch_bounds__(256, 2) void attn_mma_k(const float* __restrict__ rpb0,
                                                     int jp)
{
    extern __shared__ uint32_t sma[];
    uint32_t* QP = sma;
    const uint32_t sa0 = smem_u32(sma);
    const uint32_t qb_sa = sa0;

    const int tid = threadIdx.x;
    const int wid = tid >> 5, ln = tid & 31;
    const int g = ln >> 2, t = ln & 3;
    const int j = jp, bhl = blockIdx.x;
    const int qt = blockIdx.y;
    const int h = bhl & 15, bw = bhl >> 4;
    const int q0 = qt << 7;
    const int tq = (qt << 1) + (wid >> 2);
    const int mrow = wid << 4;
    const float* rpb = rpb0 + j * 15 * HH;

    const uint32_t* Qb  = (const uint32_t*)(g_Q  + (size_t)j * QSPAN);
    const uint32_t* Kb  = (const uint32_t*)(g_K  + (size_t)j * QSPAN);
    const uint32_t* Vtb = (const uint32_t*)(g_Vt + (size_t)j * QSPAN);

    const int arow_l = ((ln >> 3) & 1) * 8 + (ln & 7);
    const int akh = ln >> 4;
    const int aoff = ((mrow + arow_l) * 36 + akh * 4) << 2;
    const int brow_l = ((ln >> 4) * 8) + (ln & 7);
    const int bkh = (ln >> 3) & 1;
    int boff[4];
    #pragma unroll
    for (int pi = 0; pi < 4; pi++)
        boff[pi] = ((pi * 16 + brow_l) * 36 + bkh * 4) << 2;

    {   // stage Q
        const int r = tid >> 1, cu = (tid & 1) << 4;
        const uint32_t* qs = Qb + ((size_t)(bhl * 512 + q0 + r)) * 32 + cu;
        #pragma unroll
        for (int u = 0; u < 4; u++)
            *(uint4*)&QP[r * 36 + cu + u * 4] = *(const uint4*)(qs + u * 4);
    }
    __syncthreads();

    uint32_t af[4][4];
    #pragma unroll
    for (int kt4 = 0; kt4 < 4; kt4++)
        ldsm4(af[kt4], qb_sa + aoff + (kt4 << 5));
    __syncthreads();

    float oc[8][4];
    #pragma unroll
    for (int i = 0; i < 8; i++)
        #pragma unroll
        for (int q = 0; q < 4; q++) oc[i][q] = 0.f;
    float m_i[2] = {-1e30f, -1e30f}, l_i[2] = {0.f, 0.f};

    const int sr = tid >> 2, scu = (tid & 3) << 3;

    uint4 pk[2], pv[2];
#define LOADKV(kt_) do {                                                          \
    const uint32_t* ks_ = Kb + ((size_t)(bhl * 512 + (kt_) * 64 + sr)) * 32 + scu;\
    pk[0] = *(const uint4*)ks_;                                                   \
    pk[1] = *(const uint4*)(ks_ + 4);                                             \
    const uint32_t* vs_ = Vtb + ((size_t)(bhl * 64 + sr)) * 256 + (kt_) * 32 + scu;\
    pv[0] = *(const uint4*)vs_;                                                   \
    pv[1] = *(const uint4*)(vs_ + 4);                                             \
} while (0)

    LOADKV(0);

    for (int kt = 0; kt < 8; kt++) {
        const float bias_s = rpb[(tq - kt + 7) * HH + h];
        const int buf = kt & 1;
        uint32_t* Ktb  = sma + 128 * 36 + buf * KVBUF;
        uint32_t* Vtbs = Ktb + 64 * 36;
        *(uint4*)&Ktb[sr * 36 + scu]      = pk[0];
        *(uint4*)&Ktb[sr * 36 + scu + 4]  = pk[1];
        *(uint4*)&Vtbs[sr * 36 + scu]     = pv[0];
        *(uint4*)&Vtbs[sr * 36 + scu + 4] = pv[1];
        __syncthreads();
        if (kt < 7) LOADKV(kt + 1);
        const uint32_t kb_sa = sa0 + ((128 * 36 + buf * KVBUF) << 2);
        const uint32_t vb_sa = kb_sa + (64 * 36 << 2);

        float sc[8][4];
        #pragma unroll
        for (int i = 0; i < 8; i++)
            #pragma unroll
            for (int q = 0; q < 4; q++) sc[i][q] = 0.f;
        #pragma unroll
        for (int kt4 = 0; kt4 < 4; kt4++) {
            uint32_t bfr[4][4];
            #pragma unroll
            for (int pi = 0; pi < 4; pi++)
                ldsm4(bfr[pi], kb_sa + boff[pi] + (kt4 << 5));
            #pragma unroll
            for (int ni = 0; ni < 8; ni++)
                mma16(sc[ni], af[kt4], &bfr[ni >> 1][(ni & 1) * 2]);
        }

        #pragma unroll
        for (int hr = 0; hr < 2; hr++) {
            float mx = -1e30f;
            #pragma unroll
            for (int ni = 0; ni < 8; ni++)
                mx = fmaxf(mx, fmaxf(sc[ni][2*hr], sc[ni][2*hr+1]));
            mx += bias_s;
            mx = fmaxf(mx, __shfl_xor_sync(0xffffffffu, mx, 1));
            mx = fmaxf(mx, __shfl_xor_sync(0xffffffffu, mx, 2));
            const float mn = fmaxf(m_i[hr], mx);
            const float fac = __expf(m_i[hr] - mn);
            m_i[hr] = mn;
            float sum = 0.f;
            const int prow = (mrow + hr * 8 + g) * 36;
            #pragma unroll
            for (int ni = 0; ni < 8; ni++) {
                float p0 = __expf(sc[ni][2*hr]   + bias_s - mn);
                float p1 = __expf(sc[ni][2*hr+1] + bias_s - mn);
                sum += p0 + p1;
                QP[prow + ni * 4 + t] = pack2(p0, p1);
            }
            sum += __shfl_xor_sync(0xffffffffu, sum, 1);
            sum += __shfl_xor_sync(0xffffffffu, sum, 2);
            l_i[hr] = l_i[hr] * fac + sum;
            #pragma unroll
            for (int ni = 0; ni < 8; ni++) {
                oc[ni][2*hr]   *= fac;
                oc[ni][2*hr+1] *= fac;
            }
        }
        __syncwarp();

        #pragma unroll
        for (int kp = 0; kp < 4; kp++) {
            uint32_t pf[4], vfr[4][4];
            ldsm4(pf, qb_sa + aoff + (kp << 5));
            #pragma unroll
            for (int pi = 0; pi < 4; pi++)
                ldsm4(vfr[pi], vb_sa + boff[pi] + (kp << 5));
            #pragma unroll
            for (int ni = 0; ni < 8; ni++)
                mma16(oc[ni], pf, &vfr[ni >> 1][(ni & 1) * 2]);
        }
    }

    const float inv0 = 1.0f / l_i[0], inv1 = 1.0f / l_i[1];
    #pragma unroll
    for (int hr = 0; hr < 2; hr++) {
        const float inv = hr ? inv1 : inv0;
        const int row = q0 + mrow + hr * 8 + g;
        uint32_t* dst = (uint32_t*)g_Oh
            + ((size_t)j * AROWS + bw * SSQ + row) * 512 + h * 32 + t;
        #pragma unroll
        for (int ni = 0; ni < 8; ni++)
            dst[ni * 4] = pack2(oc[ni][2*hr] * inv, oc[ni][2*hr+1] * inv);
    }
}

// ---------------------------------------------------------------------------
// Gate logits (fp16 G) + softmax + fuse (fp16 feats).
// ---------------------------------------------------------------------------
__global__ __launch_bounds__(256) void gate_fuse_k(const float* __restrict__ Wg2,
                                                   const float* __restrict__ bg2,
                                                   float* __restrict__ out)
{
    const int row = blockIdx.x, tid = threadIdx.x;
    const __half2* gh = (const __half2*)(g_Gh + (size_t)row * DG);
    float s0 = 0.f, s1 = 0.f, s2 = 0.f;
    for (int kp = tid; kp < DG / 2; kp += 256) {
        float2 x2 = __half22float2(gh[kp]);
        const int k = kp * 2;
        s0 = fmaf(x2.x, Wg2[k*3+0], fmaf(x2.y, Wg2[k*3+3], s0));
        s1 = fmaf(x2.x, Wg2[k*3+1], fmaf(x2.y, Wg2[k*3+4], s1));
        s2 = fmaf(x2.x, Wg2[k*3+2], fmaf(x2.y, Wg2[k*3+5], s2));
    }
    #pragma unroll
    for (int m = 16; m; m >>= 1) {
        s0 += __shfl_xor_sync(0xffffffffu, s0, m);
        s1 += __shfl_xor_sync(0xffffffffu, s1, m);
        s2 += __shfl_xor_sync(0xffffffffu, s2, m);
    }
    __shared__ float red[3][8];
    __shared__ float gl[3];
    int wid = tid >> 5, lane = tid & 31;
    if (lane == 0) { red[0][wid]=s0; red[1][wid]=s1; red[2][wid]=s2; }
    __syncthreads();
    if (tid < 3) {
        float s = bg2[tid];
        #pragma unroll
        for (int w = 0; w < 8; w++) s += red[tid][w];
        gl[tid] = s;
    }
    __syncthreads();
    float a0 = gl[0], a1 = gl[1], a2 = gl[2];
    float mx = fmaxf(a0, fmaxf(a1, a2));
    float e0 = __expf(a0-mx), e1 = __expf(a1-mx), e2 = __expf(a2-mx);
    float inv = 1.0f / (e0 + e1 + e2);
    e0 *= inv; e1 *= inv; e2 *= inv;
    const uint2* f0 = (const uint2*)(g_featsh + (size_t)0*FEATSZ + (size_t)row*DD);
    const uint2* f1 = (const uint2*)(g_featsh + (size_t)1*FEATSZ + (size_t)row*DD);
    const uint2* f2 = (const uint2*)(g_featsh + (size_t)2*FEATSZ + (size_t)row*DD);
    float4* o4 = (float4*)(out + (size_t)row * DD);
    uint2 u0 = f0[tid], u1 = f1[tid], u2 = f2[tid];
    float2 a_0 = __half22float2(*(__half2*)&u0.x), a_1 = __half22float2(*(__half2*)&u0.y);
    float2 b_0 = __half22float2(*(__half2*)&u1.x), b_1 = __half22float2(*(__half2*)&u1.y);
    float2 c_0 = __half22float2(*(__half2*)&u2.x), c_1 = __half22float2(*(__half2*)&u2.y);
    o4[tid] = make_float4(e0*a_0.x + e1*b_0.x + e2*c_0.x,
                          e0*a_0.y + e1*b_0.y + e2*c_0.y,
                          e0*a_1.x + e1*b_1.x + e2*c_1.x,
                          e0*a_1.y + e1*b_1.y + e2*c_1.y);
}

// ---------------------------------------------------------------------------
// Launch: per-modality chain pipelining across 3 streams.
// ---------------------------------------------------------------------------
extern "C" void kernel_launch(void* const* d_in, const int* in_sizes, int n_in,
                              void* d_out, int out_size)
{
    const float* audio = (const float*)d_in[0];
    const float* video = (const float*)d_in[1];
    const float* image = (const float*)d_in[2];
    const float* Wq = (const float*)d_in[3];
    const float* Wk = (const float*)d_in[4];
    const float* Wv = (const float*)d_in[5];
    const float* Wp = (const float*)d_in[6];
    const float* bq = (const float*)d_in[7];
    const float* bk = (const float*)d_in[8];
    const float* bv = (const float*)d_in[9];
    const float* bp = (const float*)d_in[10];
    const float* qn = (const float*)d_in[11];
    const float* kn = (const float*)d_in[12];
    const float* rpb = (const float*)d_in[13];
    const float* Wg1 = (const float*)d_in[14];
    const float* bg1 = (const float*)d_in[15];
    const float* Wg2 = (const float*)d_in[16];
    const float* bg2 = (const float*)d_in[17];
    float* out = (float*)d_out;

    static int init_done = 0;
    static cudaStream_t s2, sA, sB;
    static cudaEvent_t ev0, evW, evG, evC, evA, evB;
    if (!init_done) {
        cudaStreamCreateWithFlags(&s2, cudaStreamNonBlocking);
        cudaStreamCreateWithFlags(&sA, cudaStreamNonBlocking);
        cudaStreamCreateWithFlags(&sB, cudaStreamNonBlocking);
        cudaEventCreateWithFlags(&ev0, cudaEventDisableTiming);
        cudaEventCreateWithFlags(&evW, cudaEventDisableTiming);
        cudaEventCreateWithFlags(&evG, cudaEventDisableTiming);
        cudaEventCreateWithFlags(&evC, cudaEventDisableTiming);
        cudaEventCreateWithFlags(&evA, cudaEventDisableTiming);
        cudaEventCreateWithFlags(&evB, cudaEventDisableTiming);
        cudaFuncSetAttribute(tgemm_k<0>, cudaFuncAttributeMaxDynamicSharedMemorySize, GSMEMB);
        cudaFuncSetAttribute(tgemm_k<2>, cudaFuncAttributeMaxDynamicSharedMemorySize, GSMEMB);
        cudaFuncSetAttribute(tgemm_k<3>, cudaFuncAttributeMaxDynamicSharedMemorySize, GSMEMB);
        cudaFuncSetAttribute(attn_mma_k, cudaFuncAttributeMaxDynamicSharedMemorySize, ASMEM);
        init_done = 1;
    }

    dim3 blk(256), blkG(512);
    dim3 gQKV(24, 16), gATT(128, 4), gPRJ(8, 16);

    // fork: weight transposes on s2, activation conversion on main
    cudaEventRecord(ev0, 0);
    cudaStreamWaitEvent(s2, ev0, 0);
    transW_k<<<dim3(32, 32, 12), blk, 0, s2>>>(Wq, Wk, Wv, Wp);
    cudaEventRecord(evW, s2);
    transG_k<<<dim3(64, 96), blk, 0, s2>>>(Wg1);
    cudaEventRecord(evG, s2);

    conv_k<<<dim3(2048, 3), blk>>>(audio, video, image);
    cudaEventRecord(evC, 0);

    // modality chains: j=0 on main, j=1 on sA, j=2 on sB
    cudaStreamWaitEvent(0, evW, 0);
    cudaStreamWaitEvent(sA, evC, 0); cudaStreamWaitEvent(sA, evW, 0);
    cudaStreamWaitEvent(sB, evC, 0); cudaStreamWaitEvent(sB, evW, 0);

    tgemm_k<0><<<gQKV, blkG, GSMEMB, 0>>>(bq, bk, bv, qn, kn, 0, DD);
    tgemm_k<0><<<gQKV, blkG, GSMEMB, sA>>>(bq, bk, bv, qn, kn, 1, DD);
    tgemm_k<0><<<gQKV, blkG, GSMEMB, sB>>>(bq, bk, bv, qn, kn, 2, DD);

    attn_mma_k<<<gATT, blk, ASMEM, 0>>>(rpb, 0);
    attn_mma_k<<<gATT, blk, ASMEM, sA>>>(rpb, 1);
    attn_mma_k<<<gATT, blk, ASMEM, sB>>>(rpb, 2);

    tgemm_k<2><<<gPRJ, blkG, GSMEMB, 0>>>(bp, audio, video, image, nullptr, 0, DD);
    tgemm_k<2><<<gPRJ, blkG, GSMEMB, sA>>>(bp, audio, video, image, nullptr, 1, DD);
    cudaEventRecord(evA, sA);
    tgemm_k<2><<<gPRJ, blkG, GSMEMB, sB>>>(bp, audio, video, image, nullptr, 2, DD);
    cudaEventRecord(evB, sB);

    // join: gate needs all feats + transG
    cudaStreamWaitEvent(0, evA, 0);
    cudaStreamWaitEvent(0, evB, 0);
    cudaStreamWaitEvent(0, evG, 0);
    tgemm_k<3><<<dim3(16, 16), blkG, GSMEMB>>>(bg1, nullptr, nullptr, nullptr, nullptr, 0, K3D);
    gate_fuse_k<<<BTLR, 256>>>(Wg2, bg2, out);
}